// round 11
// baseline (speedup 1.0000x reference)
#include <cuda_runtime.h>
#include <cuda_fp16.h>

#define NN 10000
#define TT 50
#define Bn 2
#define Hn 64
#define BH 128          // Bn*Hn
#define IND 128         // input feature dim
#define EMAX 160000
#define GRID 592        // 148 SMs x 4 blocks -- co-resident via __launch_bounds__(256,4)
#define NPB 17          // nodes per block: 592*17 = 10064 >= 10000

typedef unsigned long long u64;

// ---------------- device scratch (no allocation allowed) ----------------
__device__ __half d_hw[2][NN * BH];         // double-buffered fp16 hw = h @ W (gather operand)
__device__ int    d_deg_in[NN];
__device__ int    d_deg_out[NN];
__device__ float  d_norm_s[NN];
__device__ float  d_norm_d[NN];
__device__ int    d_row_ptr[NN + 1];
__device__ int    d_fill_ptr[NN];
__device__ int2   d_csr[EMAX];              // (src, weight-as-int-bits)
__device__ float  d_xproj[3 * BH];          // [r|z|h][b][j]
__device__ int    g_bar;                    // global barrier arrivals
__device__ int    g_gen;                    // global barrier generation

// ---------------- packed f32x2 helpers (Blackwell FFMA2) ----------------
__device__ __forceinline__ u64 pack2(float lo, float hi) {
    u64 r; asm("mov.b64 %0, {%1, %2};" : "=l"(r) : "f"(lo), "f"(hi)); return r;
}
__device__ __forceinline__ void unpack2(u64 v, float& lo, float& hi) {
    asm("mov.b64 {%0, %1}, %2;" : "=f"(lo), "=f"(hi) : "l"(v));
}
__device__ __forceinline__ void ffma2(u64& d, u64 a, u64 b) {
    asm("fma.rn.f32x2 %0, %1, %2, %0;" : "+l"(d) : "l"(a), "l"(b));
}

// ---------------- precompute kernels ----------------
__global__ void init_kernel() {
    int i0 = blockIdx.x * blockDim.x + threadIdx.x;
    int stride = gridDim.x * blockDim.x;
    for (int i = i0; i < NN; i += stride) { d_deg_in[i] = 0; d_deg_out[i] = 0; }
    if (i0 == 0) { g_bar = 0; }
}

__global__ void hist_kernel(const int* __restrict__ src, const int* __restrict__ dst, int E) {
    int e = blockIdx.x * blockDim.x + threadIdx.x;
    if (e < E) {
        atomicAdd(&d_deg_out[src[e]], 1);
        atomicAdd(&d_deg_in[dst[e]], 1);
    }
}

// norms + fast single-block exclusive scan (reg-local + 2-level warp scan)
__global__ void scan_kernel() {
    __shared__ int wsum[32];
    int tid = threadIdx.x;                 // 1024 threads
    for (int i = tid; i < NN; i += 1024) {
        d_norm_s[i] = rsqrtf((float)max(d_deg_out[i], 1));
        d_norm_d[i] = rsqrtf((float)max(d_deg_in[i], 1));
    }
    const int PER = (NN + 1023) / 1024;    // 10
    int base = tid * PER;
    int loc[PER];
    int s = 0;
    #pragma unroll
    for (int k = 0; k < PER; k++) {
        int i = base + k;
        int v = (i < NN) ? d_deg_in[i] : 0;
        loc[k] = s; s += v;
    }
    int lane = tid & 31, w = tid >> 5;
    int ps = s;
    #pragma unroll
    for (int off = 1; off < 32; off <<= 1) {
        int t = __shfl_up_sync(0xffffffffu, ps, off);
        if (lane >= off) ps += t;
    }
    if (lane == 31) wsum[w] = ps;
    __syncthreads();
    if (w == 0) {
        int v = wsum[lane];
        #pragma unroll
        for (int off = 1; off < 32; off <<= 1) {
            int t = __shfl_up_sync(0xffffffffu, v, off);
            if (lane >= off) v += t;
        }
        wsum[lane] = v;
    }
    __syncthreads();
    int warpoff = (w == 0) ? 0 : wsum[w - 1];
    int excl = warpoff + ps - s;
    #pragma unroll
    for (int k = 0; k < PER; k++) {
        int i = base + k;
        if (i < NN) {
            int rp = excl + loc[k];
            d_row_ptr[i] = rp;
            d_fill_ptr[i] = rp;
        }
    }
    if (tid == 1023) d_row_ptr[NN] = wsum[31];
}

__global__ void scatter_kernel(const int* __restrict__ src, const int* __restrict__ dst, int E) {
    int e = blockIdx.x * blockDim.x + threadIdx.x;
    if (e < E) {
        int s = src[e], d = dst[e];
        int pos = atomicAdd(&d_fill_ptr[d], 1);
        float w = d_norm_d[d] * d_norm_s[s];
        d_csr[pos] = make_int2(s, __float_as_int(w));
    }
}

// time-invariant input projections: xproj[p][b][j] = x[b] @ W_p + b_p
__global__ void xproj_kernel(const float* __restrict__ x,
                             const float* __restrict__ wr, const float* __restrict__ br,
                             const float* __restrict__ wz, const float* __restrict__ bz,
                             const float* __restrict__ wh, const float* __restrict__ bh) {
    __shared__ float xs[Bn * IND];
    int tid = threadIdx.x;
    if (tid < Bn * IND) xs[tid] = x[tid];
    __syncthreads();
    if (tid < 3 * BH) {
        int p = tid / BH, r = tid % BH, b = r / Hn, j = r % Hn;
        const float* W    = (p == 0) ? wr : (p == 1) ? wz : wh;
        const float* bias = (p == 0) ? br : (p == 1) ? bz : bh;
        float s = bias[j];
        #pragma unroll 8
        for (int k = 0; k < IND; k++)
            s += xs[b * IND + k] * W[k * Hn + j];
        d_xproj[tid] = s;
    }
}

// accumulate one fp16 message (uint2 = 4 halves) with packed FFMA2
__device__ __forceinline__ void acc_msg(u64& a01, u64& a23, float w, uint2 v) {
    float2 fa = __half22float2(*(__half2*)&v.x);
    float2 fb = __half22float2(*(__half2*)&v.y);
    u64 ww = pack2(w, w);
    ffma2(a01, ww, pack2(fa.x, fa.y));
    ffma2(a23, ww, pack2(fb.x, fb.y));
}

// sense-reversing grid-wide barrier (all GRID blocks co-resident)
__device__ __forceinline__ void grid_barrier() {
    __syncthreads();
    if (threadIdx.x == 0) {
        __threadfence();
        int gen = *(volatile int*)&g_gen;
        if (atomicAdd(&g_bar, 1) == GRID - 1) {
            g_bar = 0;
            __threadfence();
            atomicAdd(&g_gen, 1);
        } else {
            while (*(volatile int*)&g_gen == gen) { }
            __threadfence();
        }
    }
    __syncthreads();
}

__device__ __forceinline__ float fsigm(float x) {
    return __fdividef(1.f, 1.f + __expf(-x));
}

// ---------------- persistent fused GCN-GRU ----------------
// h state lives in SMEM (each block owns NPB nodes for all 50 steps).
// phase A: hw = h @ W  (publish fp16 to global)      [uses g = A(hW) = (Ah)W]
// barrier
// phase B: gather g = A_norm @ hw per node -> gates -> h update in smem -> out
__global__ __launch_bounds__(256, 4) void persist_kernel(
    const float* __restrict__ gcn_w, const float* __restrict__ gcn_b,
    float* __restrict__ out) {
    __shared__ __align__(16) float hs[NPB * BH];     // 8704 B: persistent h state
    __shared__ __align__(16) u64 Wp_s[32 * 64];      // 16384 B: W packed f32x2, kp-major

    int tid = threadIdx.x;
    int warp = tid >> 5, lane = tid & 31;
    int node0 = blockIdx.x * NPB;
    int nb = NN - node0;
    if (nb > NPB) nb = NPB;
    if (nb < 0) nb = 0;

    // pack W: Wp_s[kp*64 + j] = (W[2kp][j], W[2kp+1][j])
    for (int i = tid; i < 32 * 64; i += 256) {
        int kp = i >> 6, j = i & 63;
        Wp_s[i] = pack2(gcn_w[(2 * kp) * 64 + j], gcn_w[(2 * kp + 1) * 64 + j]);
    }
    // zero h state
    for (int i = tid; i < NPB * BH; i += 256) hs[i] = 0.f;

    // per-lane gate constants: this lane always handles channels bj = lane*4..+3
    int lane4 = lane * 4;
    float4 xr4 = *(const float4*)&d_xproj[lane4];
    float4 xz4 = *(const float4*)&d_xproj[BH + lane4];
    float4 xh4 = *(const float4*)&d_xproj[2 * BH + lane4];
    float4 gb4 = *(const float4*)&gcn_b[lane4 & 63];
    int bsel = lane >> 4;                 // batch index for this lane's channels
    __syncthreads();

    for (int t = 0; t < TT; t++) {
        // ---- phase A: hw[node][bj] = sum_k hs[node][b*64+k] * W[k][j] ----
        __half* __restrict__ hw_w = d_hw[t & 1];
        for (int o = tid; o < nb * 64; o += 256) {
            int ln = o >> 6;
            int cp = o & 63;              // channel-pair; bj0 = 2*cp
            int b  = cp >> 5;
            int j0 = (2 * cp) & 63;
            const float* hrow = &hs[ln * BH + (b << 6)];
            u64 acc0 = 0, acc1 = 0;
            #pragma unroll
            for (int kp = 0; kp < 32; kp++) {
                u64 hp = *(const u64*)&hrow[2 * kp];      // LDS64 broadcast
                ffma2(acc0, hp, Wp_s[kp * 64 + j0]);
                ffma2(acc1, hp, Wp_s[kp * 64 + j0 + 1]);
            }
            float s0a, s0b, s1a, s1b;
            unpack2(acc0, s0a, s0b); unpack2(acc1, s1a, s1b);
            __half2 hv = __floats2half2_rn(s0a + s0b, s1a + s1b);
            __stcg((__half2*)&hw_w[(node0 + ln) * BH + 2 * cp], hv);
        }

        grid_barrier();   // all hw published before any gather reads

        // ---- phase B: gather g directly, gates, update h in smem, write out ----
        const __half* __restrict__ hw_r = d_hw[t & 1];
        for (int ln = warp; ln < nb; ln += 8) {
            int node = node0 + ln;
            int p = __ldg(&d_row_ptr[node]), e = __ldg(&d_row_ptr[node + 1]);
            u64 a01 = 0, a23 = 0;
            for (; p + 4 <= e; p += 4) {
                int2 e0 = __ldg(&d_csr[p]);
                int2 e1 = __ldg(&d_csr[p + 1]);
                int2 e2 = __ldg(&d_csr[p + 2]);
                int2 e3 = __ldg(&d_csr[p + 3]);
                uint2 v0 = __ldcg((const uint2*)&hw_r[e0.x * BH + lane4]);
                uint2 v1 = __ldcg((const uint2*)&hw_r[e1.x * BH + lane4]);
                uint2 v2 = __ldcg((const uint2*)&hw_r[e2.x * BH + lane4]);
                uint2 v3 = __ldcg((const uint2*)&hw_r[e3.x * BH + lane4]);
                acc_msg(a01, a23, __int_as_float(e0.y), v0);
                acc_msg(a01, a23, __int_as_float(e1.y), v1);
                acc_msg(a01, a23, __int_as_float(e2.y), v2);
                acc_msg(a01, a23, __int_as_float(e3.y), v3);
            }
            for (; p < e; p++) {
                int2 ee = __ldg(&d_csr[p]);
                uint2 v = __ldcg((const uint2*)&hw_r[ee.x * BH + lane4]);
                acc_msg(a01, a23, __int_as_float(ee.y), v);
            }
            float4 g4;
            unpack2(a01, g4.x, g4.y); unpack2(a23, g4.z, g4.w);
            g4.x += gb4.x; g4.y += gb4.y; g4.z += gb4.z; g4.w += gb4.w;

            float4 hold = *(const float4*)&hs[ln * BH + lane4];
            float4 hn;
            {
                float r = fsigm(xr4.x + g4.x), z = fsigm(xz4.x + g4.x);
                float ht = 2.f * fsigm(2.f * (xh4.x + r * g4.x)) - 1.f;
                hn.x = (1.f - z) * hold.x + z * ht;
            }
            {
                float r = fsigm(xr4.y + g4.y), z = fsigm(xz4.y + g4.y);
                float ht = 2.f * fsigm(2.f * (xh4.y + r * g4.y)) - 1.f;
                hn.y = (1.f - z) * hold.y + z * ht;
            }
            {
                float r = fsigm(xr4.z + g4.z), z = fsigm(xz4.z + g4.z);
                float ht = 2.f * fsigm(2.f * (xh4.z + r * g4.z)) - 1.f;
                hn.z = (1.f - z) * hold.z + z * ht;
            }
            {
                float r = fsigm(xr4.w + g4.w), z = fsigm(xz4.w + g4.w);
                float ht = 2.f * fsigm(2.f * (xh4.w + r * g4.w)) - 1.f;
                hn.w = (1.f - z) * hold.w + z * ht;
            }
            *(float4*)&hs[ln * BH + lane4] = hn;
            *(float4*)&out[((size_t)(bsel * TT + t) * NN + node) * Hn + (lane4 & 63)] = hn;
        }

        __syncthreads();   // hs updates visible to phase A of next step (intra-block only)
    }
}

// ---------------- launch ----------------
extern "C" void kernel_launch(void* const* d_in, const int* in_sizes, int n_in,
                              void* d_out, int out_size) {
    const float* x    = (const float*)d_in[0];
    const int*   src  = (const int*)  d_in[1];
    const int*   dst  = (const int*)  d_in[2];
    const float* wr   = (const float*)d_in[3];
    const float* br   = (const float*)d_in[4];
    const float* wz   = (const float*)d_in[5];
    const float* bz   = (const float*)d_in[6];
    const float* wh   = (const float*)d_in[7];
    const float* bh   = (const float*)d_in[8];
    const float* gw   = (const float*)d_in[9];
    const float* gb   = (const float*)d_in[10];
    float* out = (float*)d_out;
    int E = in_sizes[1];

    init_kernel<<<40, 256>>>();
    hist_kernel<<<(E + 255) / 256, 256>>>(src, dst, E);
    scan_kernel<<<1, 1024>>>();
    scatter_kernel<<<(E + 255) / 256, 256>>>(src, dst, E);
    xproj_kernel<<<1, 512>>>(x, wr, br, wz, bz, wh, bh);
    persist_kernel<<<GRID, 256>>>(gw, gb, out);
}

// round 14
// speedup vs baseline: 1.6323x; 1.6323x over previous
#include <cuda_runtime.h>
#include <cuda_fp16.h>

#define NN 10000
#define TT 50
#define Bn 2
#define Hn 64
#define BH 128          // Bn*Hn
#define IND 128         // input feature dim
#define EMAX 160000
#define GRID 444        // 148 SMs x 3 blocks -- co-resident via __launch_bounds__(256,3)
#define NPB 23          // nodes per block: 444*23 = 10212 >= 10000

typedef unsigned long long u64;
typedef unsigned int u32;

// ---------------- device scratch (no allocation allowed) ----------------
__device__ __half d_hh[2][NN * BH];         // double-buffered fp16 hidden state (gather operand)
__device__ int    d_deg_in[NN];
__device__ int    d_deg_out[NN];
__device__ float  d_norm_s[NN];
__device__ float  d_norm_d[NN];
__device__ int    d_row_ptr[NN + 1];
__device__ int    d_fill_ptr[NN];
__device__ int2   d_csr[EMAX];              // (src, weight-as-int-bits)
__device__ int    g_bar;                    // global barrier arrivals (static zero-init)
__device__ int    g_gen;                    // global barrier generation

// ---------------- packed f32x2 helpers (Blackwell FFMA2) ----------------
__device__ __forceinline__ u64 pack2(float lo, float hi) {
    u64 r; asm("mov.b64 %0, {%1, %2};" : "=l"(r) : "f"(lo), "f"(hi)); return r;
}
__device__ __forceinline__ void unpack2(u64 v, float& lo, float& hi) {
    asm("mov.b64 {%0, %1}, %2;" : "=f"(lo), "=f"(hi) : "l"(v));
}
__device__ __forceinline__ void ffma2(u64& d, u64 a, u64 b) {
    asm("fma.rn.f32x2 %0, %1, %2, %0;" : "+l"(d) : "l"(a), "l"(b));
}

// accumulate one fp16 message (uint2 = 4 halves) with packed FFMA2
__device__ __forceinline__ void acc_msg(u64& a01, u64& a23, float w, uint2 v) {
    float2 fa = __half22float2(*(__half2*)&v.x);
    float2 fb = __half22float2(*(__half2*)&v.y);
    u64 ww = pack2(w, w);
    ffma2(a01, ww, pack2(fa.x, fa.y));
    ffma2(a23, ww, pack2(fb.x, fb.y));
}

// sense-reversing grid-wide barrier (all GRID blocks co-resident)
__device__ __forceinline__ void grid_barrier() {
    __syncthreads();
    if (threadIdx.x == 0) {
        __threadfence();
        int gen = *(volatile int*)&g_gen;
        if (atomicAdd(&g_bar, 1) == GRID - 1) {
            g_bar = 0;
            __threadfence();
            atomicAdd(&g_gen, 1);
        } else {
            while (*(volatile int*)&g_gen == gen) { }
            __threadfence();
        }
    }
    __syncthreads();
}

__device__ __forceinline__ float fsigm(float x) {
    return __fdividef(1.f, 1.f + __expf(-x));
}

// ================= ONE kernel: precompute + all 50 GCN-GRU timesteps =================
__global__ __launch_bounds__(256, 3) void mega_kernel(
    const float* __restrict__ x,
    const int*   __restrict__ src,  const int* __restrict__ dst,
    const float* __restrict__ wr,   const float* __restrict__ br,
    const float* __restrict__ wz,   const float* __restrict__ bz,
    const float* __restrict__ wh,   const float* __restrict__ bh,
    const float* __restrict__ gcn_w, const float* __restrict__ gcn_b,
    float* __restrict__ out, int E) {

    __shared__ __align__(16) float hs[NPB * BH];     // persistent fp32 h state (this block's nodes)
    __shared__ __align__(16) float agg_s[NPB * BH];  // staged aggregation
    __shared__ float xg_s[3 * BH];                   // xr|xz|xh projections
    __shared__ int   wsum_s[8];

    int tid  = threadIdx.x;
    int warp = tid >> 5, lane = tid & 31;
    int gtid = blockIdx.x * 256 + tid;
    int gstride = GRID * 256;

    int node0 = blockIdx.x * NPB;
    int nb = NN - node0;
    if (nb > NPB) nb = NPB;
    if (nb < 0) nb = 0;

    // ---------- pre 0: zero state + degree arrays ----------
    for (int i = gtid; i < NN * BH / 2; i += gstride)
        ((__half2*)d_hh[0])[i] = __floats2half2_rn(0.f, 0.f);
    for (int i = gtid; i < NN; i += gstride) { d_deg_in[i] = 0; d_deg_out[i] = 0; }
    // per-block: zero h state, compute xproj locally (x-only, no cross-block dep)
    for (int i = tid; i < NPB * BH; i += 256) hs[i] = 0.f;
    {
        // xs in agg_s as temp
        if (tid < Bn * IND) agg_s[tid] = x[tid];
        __syncthreads();
        for (int i = tid; i < 3 * BH; i += 256) {
            int p = i / BH, r = i % BH, b = r / Hn, j = r % Hn;
            const float* W    = (p == 0) ? wr : (p == 1) ? wz : wh;
            const float* bias = (p == 0) ? br : (p == 1) ? bz : bh;
            float s = bias[j];
            #pragma unroll 8
            for (int k = 0; k < IND; k++)
                s += agg_s[b * IND + k] * W[k * Hn + j];
            xg_s[i] = s;
        }
        __syncthreads();
    }
    grid_barrier();   // degrees zeroed everywhere

    // ---------- pre 1: degree histogram ----------
    for (int e = gtid; e < E; e += gstride) {
        atomicAdd(&d_deg_out[src[e]], 1);
        atomicAdd(&d_deg_in[dst[e]], 1);
    }
    grid_barrier();

    // ---------- pre 2: norms (all blocks) + exclusive scan (block 0) ----------
    for (int i = gtid; i < NN; i += gstride) {
        d_norm_s[i] = rsqrtf((float)max(d_deg_out[i], 1));
        d_norm_d[i] = rsqrtf((float)max(d_deg_in[i], 1));
    }
    if (blockIdx.x == 0) {
        const int PER = (NN + 255) / 256;       // 40 contiguous elems per thread
        int base = tid * PER;
        int s = 0;
        for (int k = 0; k < PER; k++) {
            int i = base + k;
            if (i < NN) s += d_deg_in[i];
        }
        int ps = s;
        #pragma unroll
        for (int off = 1; off < 32; off <<= 1) {
            int tv = __shfl_up_sync(0xffffffffu, ps, off);
            if (lane >= off) ps += tv;
        }
        if (lane == 31) wsum_s[warp] = ps;
        __syncthreads();
        if (warp == 0 && lane < 8) {
            int v = wsum_s[lane];
            #pragma unroll
            for (int off = 1; off < 8; off <<= 1) {
                int tv = __shfl_up_sync(0xffu, v, off);
                if (lane >= off) v += tv;
            }
            wsum_s[lane] = v;
        }
        __syncthreads();
        int warpoff = (warp == 0) ? 0 : wsum_s[warp - 1];
        int run = warpoff + ps - s;             // exclusive prefix
        for (int k = 0; k < PER; k++) {
            int i = base + k;
            if (i < NN) {
                d_row_ptr[i] = run;
                d_fill_ptr[i] = run;
                run += d_deg_in[i];
            }
        }
        if (tid == 255) d_row_ptr[NN] = wsum_s[7];
        __syncthreads();
    }
    grid_barrier();

    // ---------- pre 3: CSR scatter with fused edge weight ----------
    for (int e = gtid; e < E; e += gstride) {
        int s = src[e], d = dst[e];
        int pos = atomicAdd(&d_fill_ptr[d], 1);
        float w = d_norm_d[d] * d_norm_s[s];
        d_csr[pos] = make_int2(s, __float_as_int(w));
    }

    // ---------- per-thread persistent constants ----------
    int j  = tid & 63;                  // output channel
    int pg = tid >> 6;                  // item group 0..3
    u32 Whreg[32];                      // fp16 W column: (W[2k][j], W[2k+1][j]) packed
    #pragma unroll
    for (int kp = 0; kp < 32; kp++) {
        __half2 hv = __floats2half2_rn(gcn_w[(2 * kp) * 64 + j],
                                       gcn_w[(2 * kp + 1) * 64 + j]);
        Whreg[kp] = *(u32*)&hv;
    }
    float bias_j = gcn_b[j];

    grid_barrier();   // csr + hh[0] ready everywhere

    // ================= 50 timesteps =================
    for (int t = 0; t < TT; t++) {
        const __half* __restrict__ hh_prev = d_hh[t & 1];
        __half*       __restrict__ hh_next = d_hh[(t & 1) ^ 1];

        // ---- phase 1: dual-stream CSR gather (2 nodes per warp in flight) ----
        int lane4 = lane * 4;
        for (int base = 0; base < nb; base += 16) {
            int lnA = base + warp;
            int lnB = base + warp + 8;
            bool actA = lnA < nb, actB = lnB < nb;
            int pA = 0, eA = 0, pB = 0, eB = 0;
            if (actA) { pA = __ldg(&d_row_ptr[node0 + lnA]); eA = __ldg(&d_row_ptr[node0 + lnA + 1]); }
            if (actB) { pB = __ldg(&d_row_ptr[node0 + lnB]); eB = __ldg(&d_row_ptr[node0 + lnB + 1]); }
            u64 a01 = 0, a23 = 0, b01 = 0, b23 = 0;

            while (pA + 2 <= eA && pB + 2 <= eB) {
                int2 ea0 = __ldg(&d_csr[pA]);
                int2 ea1 = __ldg(&d_csr[pA + 1]);
                int2 eb0 = __ldg(&d_csr[pB]);
                int2 eb1 = __ldg(&d_csr[pB + 1]);
                uint2 va0 = __ldcg((const uint2*)&hh_prev[ea0.x * BH + lane4]);
                uint2 va1 = __ldcg((const uint2*)&hh_prev[ea1.x * BH + lane4]);
                uint2 vb0 = __ldcg((const uint2*)&hh_prev[eb0.x * BH + lane4]);
                uint2 vb1 = __ldcg((const uint2*)&hh_prev[eb1.x * BH + lane4]);
                acc_msg(a01, a23, __int_as_float(ea0.y), va0);
                acc_msg(a01, a23, __int_as_float(ea1.y), va1);
                acc_msg(b01, b23, __int_as_float(eb0.y), vb0);
                acc_msg(b01, b23, __int_as_float(eb1.y), vb1);
                pA += 2; pB += 2;
            }
            // tails (MLP-4 within a single stream)
            if (actA) {
                int p = pA;
                for (; p + 4 <= eA; p += 4) {
                    int2 e0 = __ldg(&d_csr[p]);
                    int2 e1 = __ldg(&d_csr[p + 1]);
                    int2 e2 = __ldg(&d_csr[p + 2]);
                    int2 e3 = __ldg(&d_csr[p + 3]);
                    uint2 v0 = __ldcg((const uint2*)&hh_prev[e0.x * BH + lane4]);
                    uint2 v1 = __ldcg((const uint2*)&hh_prev[e1.x * BH + lane4]);
                    uint2 v2 = __ldcg((const uint2*)&hh_prev[e2.x * BH + lane4]);
                    uint2 v3 = __ldcg((const uint2*)&hh_prev[e3.x * BH + lane4]);
                    acc_msg(a01, a23, __int_as_float(e0.y), v0);
                    acc_msg(a01, a23, __int_as_float(e1.y), v1);
                    acc_msg(a01, a23, __int_as_float(e2.y), v2);
                    acc_msg(a01, a23, __int_as_float(e3.y), v3);
                }
                for (; p < eA; p++) {
                    int2 ee = __ldg(&d_csr[p]);
                    uint2 v = __ldcg((const uint2*)&hh_prev[ee.x * BH + lane4]);
                    acc_msg(a01, a23, __int_as_float(ee.y), v);
                }
                float4 r;
                unpack2(a01, r.x, r.y); unpack2(a23, r.z, r.w);
                *(float4*)&agg_s[lnA * BH + lane4] = r;
            }
            if (actB) {
                int p = pB;
                for (; p + 4 <= eB; p += 4) {
                    int2 e0 = __ldg(&d_csr[p]);
                    int2 e1 = __ldg(&d_csr[p + 1]);
                    int2 e2 = __ldg(&d_csr[p + 2]);
                    int2 e3 = __ldg(&d_csr[p + 3]);
                    uint2 v0 = __ldcg((const uint2*)&hh_prev[e0.x * BH + lane4]);
                    uint2 v1 = __ldcg((const uint2*)&hh_prev[e1.x * BH + lane4]);
                    uint2 v2 = __ldcg((const uint2*)&hh_prev[e2.x * BH + lane4]);
                    uint2 v3 = __ldcg((const uint2*)&hh_prev[e3.x * BH + lane4]);
                    acc_msg(b01, b23, __int_as_float(e0.y), v0);
                    acc_msg(b01, b23, __int_as_float(e1.y), v1);
                    acc_msg(b01, b23, __int_as_float(e2.y), v2);
                    acc_msg(b01, b23, __int_as_float(e3.y), v3);
                }
                for (; p < eB; p++) {
                    int2 ee = __ldg(&d_csr[p]);
                    uint2 v = __ldcg((const uint2*)&hh_prev[ee.x * BH + lane4]);
                    acc_msg(b01, b23, __int_as_float(ee.y), v);
                }
                float4 r;
                unpack2(b01, r.x, r.y); unpack2(b23, r.z, r.w);
                *(float4*)&agg_s[lnB * BH + lane4] = r;
            }
        }
        __syncthreads();

        // ---- phase 2: g = agg @ W + b (fp16 W in regs, FFMA2), gates, update ----
        for (int pi = pg; pi < nb * 2; pi += 4) {
            int ln = pi >> 1, b = pi & 1;
            int node = node0 + ln;
            const float* a = &agg_s[ln * BH + b * Hn];
            u64 g2 = 0;
            #pragma unroll
            for (int k4 = 0; k4 < 16; k4++) {
                float4 av = *(const float4*)&a[k4 * 4];   // warp-broadcast LDS128
                float2 w01 = __half22float2(*(__half2*)&Whreg[2 * k4]);
                float2 w23 = __half22float2(*(__half2*)&Whreg[2 * k4 + 1]);
                ffma2(g2, pack2(av.x, av.y), pack2(w01.x, w01.y));
                ffma2(g2, pack2(av.z, av.w), pack2(w23.x, w23.y));
            }
            float glo, ghi;
            unpack2(g2, glo, ghi);
            float g = bias_j + glo + ghi;
            int bj = b * Hn + j;
            float r = fsigm(xg_s[bj] + g);
            float z = fsigm(xg_s[BH + bj] + g);
            float ht = 2.f * fsigm(2.f * (xg_s[2 * BH + bj] + r * g)) - 1.f;  // tanh
            float hold = hs[ln * BH + bj];
            float hn = (1.f - z) * hold + z * ht;
            hs[ln * BH + bj] = hn;
            __stcg(&hh_next[node * BH + bj], __float2half_rn(hn));
            out[((size_t)(b * TT + t) * NN + node) * Hn + j] = hn;
        }

        grid_barrier();   // hh_next published before next step's gather
    }
}

// ---------------- launch: ONE kernel ----------------
extern "C" void kernel_launch(void* const* d_in, const int* in_sizes, int n_in,
                              void* d_out, int out_size) {
    const float* x    = (const float*)d_in[0];
    const int*   src  = (const int*)  d_in[1];
    const int*   dst  = (const int*)  d_in[2];
    const float* wr   = (const float*)d_in[3];
    const float* br   = (const float*)d_in[4];
    const float* wz   = (const float*)d_in[5];
    const float* bz   = (const float*)d_in[6];
    const float* wh   = (const float*)d_in[7];
    const float* bh   = (const float*)d_in[8];
    const float* gw   = (const float*)d_in[9];
    const float* gb   = (const float*)d_in[10];
    float* out = (float*)d_out;
    int E = in_sizes[1];

    mega_kernel<<<GRID, 256>>>(x, src, dst, wr, br, wz, bz, wh, bh, gw, gb, out, E);
}